// round 2
// baseline (speedup 1.0000x reference)
#include <cuda_runtime.h>
#include <cstdint>

// Problem constants
#define T_STEPS 1024
#define BATCH   16
#define NHEADS  12
#define HD      64
#define NG      4
#define NCELLS  (BATCH * NHEADS)          // 192
#define CELLSTR (HD * NG)                 // 256 floats per (t,b,n)
#define TSTRIDE (NCELLS * CELLSTR)        // 49152 floats per timestep of Wx
#define OROW    ((size_t)NCELLS * HD)     // 12288 floats per timestep of out

typedef unsigned long long ull;

__device__ __forceinline__ ull pk2(float lo, float hi) {
    ull r;
    asm("mov.b64 %0, {%1, %2};" : "=l"(r) : "r"(__float_as_uint(lo)), "r"(__float_as_uint(hi)));
    return r;
}
__device__ __forceinline__ void upk2(ull v, float& lo, float& hi) {
    unsigned a, b2;
    asm("mov.b64 {%0, %1}, %2;" : "=r"(a), "=r"(b2) : "l"(v));
    lo = __uint_as_float(a);
    hi = __uint_as_float(b2);
}
// Packed dual FMA: acc.{lo,hi} += a.{lo,hi} * b.{lo,hi}  (FFMA2 in SASS)
__device__ __forceinline__ void ffma2(ull& acc, ull a, ull b) {
    asm("fma.rn.f32x2 %0, %1, %2, %0;" : "+l"(acc) : "l"(a), "l"(b));
}
__device__ __forceinline__ ull fadd2(ull a, ull b) {
    ull r;
    asm("add.rn.f32x2 %0, %1, %2;" : "=l"(r) : "l"(a), "l"(b));
    return r;
}

__device__ __forceinline__ float frcp(float x) {
    float r;
    asm("rcp.approx.f32 %0, %1;" : "=f"(r) : "f"(x));
    return r;
}
// Accurate-enough activations (MUFU.EX2 + MUFU.RCP; rel err ~1e-7)
__device__ __forceinline__ float fsigmoid(float x) {
    return frcp(1.0f + __expf(-x));
}
__device__ __forceinline__ float ftanh_f(float x) {
    float e = __expf(2.0f * x);
    return 1.0f - 2.0f * frcp(e + 1.0f);
}

// Per-cell named barrier: syncs the 256 threads of one cell slot only,
// so the two cells' recurrence chains interleave freely on the SM.
__device__ __forceinline__ void cellbar(int id) {
    asm volatile("bar.sync %0, 256;" :: "r"(id) : "memory");
}

__global__ void __launch_bounds__(512, 1)
flashrnn_lstm_kernel(const float* __restrict__ Wx,
                     const float* __restrict__ S0,
                     const float* __restrict__ R,
                     const float* __restrict__ bias,
                     float* __restrict__ out)
{
    const int tid = threadIdx.x;          // 0..511
    const int cs  = tid >> 8;             // cell slot within CTA: 0 or 1
    const int r   = tid & 255;
    const int g   = r >> 6;               // gate 0..3 (i,f,z,o)
    const int o   = r & 63;               // output element 0..63

    const int cell = blockIdx.x * 2 + cs; // 0..191
    const int n = cell % NHEADS;
    const int b = cell / NHEADS;

    __shared__ __align__(16) float sh_h[2][2][HD];       // [slot][pingpong][o]
    __shared__ __align__(16) float sh_act[2][HD][NG];    // [slot][o][gate] -> LDS.128 gather

    // ---- Load this thread's R row (R[n][g][o][0..63]) into registers, packed ----
    ull Rp[32];
    const float4* rrow = reinterpret_cast<const float4*>(
        R + (((size_t)n * NG + g) * HD + o) * HD);
#pragma unroll
    for (int k = 0; k < 16; ++k) {
        float4 v = rrow[k];
        Rp[2 * k]     = pk2(v.x, v.y);
        Rp[2 * k + 1] = pk2(v.z, v.w);
    }
    const float bv = bias[((size_t)n * NG + g) * HD + o];

    // ---- Initial states ----
    const size_t bn = (size_t)b * NHEADS + n;
    const size_t celloff = bn * HD + o;
    const float h0 = S0[bn * HD + o];
    float c = S0[(size_t)NCELLS * HD + bn * HD + o];   // replicated across the 4 g-threads

    float* out_h = out;                                 // [1025][192][64]
    float* out_c = out + (size_t)(T_STEPS + 1) * OROW;  // second state plane

    if (g == 0) {
        sh_h[cs][0][o] = h0;
        out_h[celloff] = h0;        // t = 0 initial h
    } else if (g == 1) {
        out_c[celloff] = c;         // t = 0 initial c
    }

    // ---- Wx stream pointer for this thread ----
    const float* wx = Wx + bn * CELLSTR + (size_t)o * NG + g;

    cellbar(cs);

    // Prefetch 4 timesteps of Wx
    float xc[4];
#pragma unroll
    for (int j = 0; j < 4; ++j)
        xc[j] = __ldcs(wx + (size_t)j * TSTRIDE);

    int p = 0;
    float* oh = out_h + OROW + celloff;   // points at t=1 row
    float* oc = out_c + OROW + celloff;

    for (int t0 = 0; t0 < T_STEPS; t0 += 4) {
        // Prefetch next 4 steps while computing current 4 (covers DRAM latency)
        float xn[4];
        const bool more = (t0 + 4) < T_STEPS;
#pragma unroll
        for (int j = 0; j < 4; ++j)
            xn[j] = more ? __ldcs(wx + (size_t)(t0 + 4 + j) * TSTRIDE) : 0.0f;

#pragma unroll
        for (int j = 0; j < 4; ++j) {
            // ---- gate pre-activation: x + b + R[n,g,o,:] . h ----
            ull acc0 = pk2(xc[j] + bv, 0.0f);
            ull acc1 = 0ULL, acc2 = 0ULL, acc3 = 0ULL;
            const ulonglong2* hb = reinterpret_cast<const ulonglong2*>(sh_h[cs][p]);
#pragma unroll
            for (int k = 0; k < 16; k += 2) {
                ulonglong2 hv0 = hb[k];       // LDS.128 broadcast
                ulonglong2 hv1 = hb[k + 1];
                ffma2(acc0, Rp[2 * k],     hv0.x);
                ffma2(acc1, Rp[2 * k + 1], hv0.y);
                ffma2(acc2, Rp[2 * k + 2], hv1.x);
                ffma2(acc3, Rp[2 * k + 3], hv1.y);
            }
            ull s = fadd2(fadd2(acc0, acc1), fadd2(acc2, acc3));
            float lo, hi;
            upk2(s, lo, hi);
            const float sum = lo + hi;

            // warp-uniform branch (64 threads per gate = 2 warps)
            const float a = (g == 2) ? ftanh_f(sum) : fsigmoid(sum);
            sh_act[cs][o][g] = a;
            cellbar(cs);

            // ---- cell update (redundant across the 4 g-threads; deterministic) ----
            const float4 av = *reinterpret_cast<const float4*>(sh_act[cs][o]); // i,f,z,o
            c = av.y * c + av.x * av.z;
            const float h = av.w * ftanh_f(c);

            if (g == 0) {
                sh_h[cs][p ^ 1][o] = h;   // write other buffer: no race with readers of sh_h[p]
                *oh = h;
            } else if (g == 1) {
                *oc = c;
            }
            cellbar(cs);

            p ^= 1;
            oh += OROW;
            oc += OROW;
        }
#pragma unroll
        for (int j = 0; j < 4; ++j) xc[j] = xn[j];
    }
}

extern "C" void kernel_launch(void* const* d_in, const int* in_sizes, int n_in,
                              void* d_out, int out_size)
{
    const float* Wx   = (const float*)d_in[0];  // [1024,16,12,64,4]
    const float* S0   = (const float*)d_in[1];  // [2,16,12,64]
    const float* R    = (const float*)d_in[2];  // [12,4,64,64]
    const float* bias = (const float*)d_in[3];  // [12,4,64]
    float* out = (float*)d_out;                 // [2,1025,16,12,64]

    flashrnn_lstm_kernel<<<NCELLS / 2, 512>>>(Wx, S0, R, bias, out);
}

// round 6
// speedup vs baseline: 1.0520x; 1.0520x over previous
#include <cuda_runtime.h>
#include <cstdint>

// Problem constants
#define T_STEPS 1024
#define BATCH   16
#define NHEADS  12
#define HD      64
#define NG      4
#define NCELLS  (BATCH * NHEADS)          // 192
#define CELLSTR (HD * NG)                 // 256 floats per (t,b,n)
#define TSTRIDE (NCELLS * CELLSTR)        // 49152 floats per timestep of Wx
#define OROW    ((size_t)NCELLS * HD)     // 12288 floats per timestep of out
#define PF      8                         // Wx prefetch distance (timesteps)

typedef unsigned long long ull;

__device__ __forceinline__ ull pk2(float lo, float hi) {
    ull r;
    asm("mov.b64 %0, {%1, %2};" : "=l"(r) : "r"(__float_as_uint(lo)), "r"(__float_as_uint(hi)));
    return r;
}
__device__ __forceinline__ void upk2(ull v, float& lo, float& hi) {
    unsigned a, b2;
    asm("mov.b64 {%0, %1}, %2;" : "=r"(a), "=r"(b2) : "l"(v));
    lo = __uint_as_float(a);
    hi = __uint_as_float(b2);
}
// Packed dual FMA: acc.{lo,hi} += a.{lo,hi} * b.{lo,hi}  (FFMA2 in SASS)
__device__ __forceinline__ void ffma2(ull& acc, ull a, ull b) {
    asm("fma.rn.f32x2 %0, %1, %2, %0;" : "+l"(acc) : "l"(a), "l"(b));
}
__device__ __forceinline__ ull fadd2(ull a, ull b) {
    ull r;
    asm("add.rn.f32x2 %0, %1, %2;" : "=l"(r) : "l"(a), "l"(b));
    return r;
}
__device__ __forceinline__ float frcp(float x) {
    float r;
    asm("rcp.approx.f32 %0, %1;" : "=f"(r) : "f"(x));
    return r;
}
// Accurate activations (MUFU.EX2 + MUFU.RCP; rel err ~1e-7)
__device__ __forceinline__ float fsigmoid(float x) {
    return frcp(1.0f + __expf(-x));
}
__device__ __forceinline__ float ftanh_f(float x) {
    float e = __expf(2.0f * x);
    return 1.0f - 2.0f * frcp(e + 1.0f);
}

__global__ void __launch_bounds__(256, 2)
flashrnn_lstm_kernel(const float* __restrict__ Wx,
                     const float* __restrict__ S0,
                     const float* __restrict__ R,
                     const float* __restrict__ bias,
                     float* __restrict__ out)
{
    const int cell = blockIdx.x;          // 0..191
    const int n = cell % NHEADS;
    const int b = cell / NHEADS;
    const int tid  = threadIdx.x;         // 0..255
    const int g    = tid >> 6;            // gate 0..3 (i,f,z,o)
    const int o    = tid & 63;            // output element for the dot
    const int warp = tid >> 5;            // 0..7
    const int lane = tid & 31;
    const int o0   = lane << 1;           // this thread's two c/h slots: o0, o0+1

    // Warp-private full h vector (each warp keeps its own complete copy ->
    // the dot never waits on other warps' h writes).
    __shared__ __align__(16) float sh_h[8][HD];
    // Ping-ponged activated gates [buf][gate][o]; stores conflict-free.
    __shared__ __align__(16) float sh_act[2][NG][HD];

    // ---- Load this thread's R row (R[n][g][o][0..63]) into registers, packed ----
    ull Rp[32];
    const float4* rrow = reinterpret_cast<const float4*>(
        R + (((size_t)n * NG + g) * HD + o) * HD);
#pragma unroll
    for (int k = 0; k < 16; ++k) {
        float4 v = rrow[k];
        Rp[2 * k]     = pk2(v.x, v.y);
        Rp[2 * k + 1] = pk2(v.z, v.w);
    }
    const float bv = bias[((size_t)n * NG + g) * HD + o];

    // ---- Initial states: c replicated per warp (2 slots per lane) ----
    const size_t bn = (size_t)b * NHEADS + n;
    const float2 h_init = *reinterpret_cast<const float2*>(S0 + bn * HD + o0);
    const float2 c_init = *reinterpret_cast<const float2*>(S0 + (size_t)NCELLS * HD + bn * HD + o0);
    float c0 = c_init.x, c1 = c_init.y;

    float* out_h = out;                                 // [1025][192][64]
    float* out_c = out + (size_t)(T_STEPS + 1) * OROW;  // second state plane

    *reinterpret_cast<float2*>(&sh_h[warp][o0]) = h_init;
    if (warp == 0) *reinterpret_cast<float2*>(out_h + bn * HD + o0) = h_init;  // t=0 h
    if (warp == 1) *reinterpret_cast<float2*>(out_c + bn * HD + o0) = c_init;  // t=0 c

    // ---- Wx stream pointer for this thread ----
    const float* wx = Wx + bn * CELLSTR + (size_t)o * NG + g;

    __syncwarp();  // own-warp h buffer ready

    // Prefetch PF timesteps of Wx (covers DRAM latency with wide margin)
    float xc[PF];
#pragma unroll
    for (int j = 0; j < PF; ++j)
        xc[j] = __ldcs(wx + (size_t)j * TSTRIDE);

    int buf = 0;
    float* oh = out_h + OROW + bn * HD + o0;   // t=1 row, this thread's slots
    float* oc = out_c + OROW + bn * HD + o0;

    for (int t0 = 0; t0 < T_STEPS; t0 += PF) {
        float xn[PF];
        const bool more = (t0 + PF) < T_STEPS;
#pragma unroll
        for (int j = 0; j < PF; ++j)
            xn[j] = more ? __ldcs(wx + (size_t)(t0 + PF + j) * TSTRIDE) : 0.0f;

#pragma unroll
        for (int j = 0; j < PF; ++j) {
            // ---- gate pre-activation: x + b + R[n,g,o,:] . h (own warp's copy) ----
            ull acc0 = pk2(xc[j] + bv, 0.0f);
            ull acc1 = 0ULL, acc2 = 0ULL, acc3 = 0ULL;
            const ulonglong2* hb = reinterpret_cast<const ulonglong2*>(sh_h[warp]);
#pragma unroll
            for (int k = 0; k < 16; k += 2) {
                ulonglong2 hv0 = hb[k];       // LDS.128 broadcast within warp
                ulonglong2 hv1 = hb[k + 1];
                ffma2(acc0, Rp[2 * k],     hv0.x);
                ffma2(acc1, Rp[2 * k + 1], hv0.y);
                ffma2(acc2, Rp[2 * k + 2], hv1.x);
                ffma2(acc3, Rp[2 * k + 3], hv1.y);
            }
            ull s = fadd2(fadd2(acc0, acc1), fadd2(acc2, acc3));
            float lo, hi;
            upk2(s, lo, hi);
            const float sum = lo + hi;

            const float a = (g == 2) ? ftanh_f(sum) : fsigmoid(sum);  // warp-uniform branch
            sh_act[buf][g][o] = a;
            __syncthreads();   // the ONLY block barrier per step

            // ---- warp-replicated cell update for this thread's two slots ----
            const float2 gi = *reinterpret_cast<const float2*>(&sh_act[buf][0][o0]);
            const float2 gf = *reinterpret_cast<const float2*>(&sh_act[buf][1][o0]);
            const float2 gz = *reinterpret_cast<const float2*>(&sh_act[buf][2][o0]);
            const float2 go = *reinterpret_cast<const float2*>(&sh_act[buf][3][o0]);
            c0 = gf.x * c0 + gi.x * gz.x;
            c1 = gf.y * c1 + gi.y * gz.y;
            float2 hv;
            hv.x = go.x * ftanh_f(c0);
            hv.y = go.y * ftanh_f(c1);

            *reinterpret_cast<float2*>(&sh_h[warp][o0]) = hv;   // own warp only
            if (warp == 0) *reinterpret_cast<float2*>(oh) = hv;
            if (warp == 1) { float2 cv = {c0, c1}; *reinterpret_cast<float2*>(oc) = cv; }
            __syncwarp();      // own-warp h visible for next dot; no block wait

            buf ^= 1;
            oh += OROW;
            oc += OROW;
        }
#pragma unroll
        for (int j = 0; j < PF; ++j) xc[j] = xn[j];
    }
}

extern "C" void kernel_launch(void* const* d_in, const int* in_sizes, int n_in,
                              void* d_out, int out_size)
{
    const float* Wx   = (const float*)d_in[0];  // [1024,16,12,64,4]
    const float* S0   = (const float*)d_in[1];  // [2,16,12,64]
    const float* R    = (const float*)d_in[2];  // [12,4,64,64]
    const float* bias = (const float*)d_in[3];  // [12,4,64]
    float* out = (float*)d_out;                 // [2,1025,16,12,64]

    flashrnn_lstm_kernel<<<NCELLS, 256>>>(Wx, S0, R, bias, out);
}

// round 9
// speedup vs baseline: 1.1606x; 1.1032x over previous
#include <cuda_runtime.h>
#include <cstdint>

// Problem constants
#define T_STEPS 1024
#define BATCH   16
#define NHEADS  12
#define HD      64
#define NG      4
#define NCELLS  (BATCH * NHEADS)          // 192
#define CELLSTR (HD * NG)                 // 256 floats per (t,b,n)
#define TSTRIDE (NCELLS * CELLSTR)        // 49152 floats per timestep of Wx
#define OROW    ((size_t)NCELLS * HD)     // 12288 floats per timestep of out
#define PF      4                         // Wx prefetch distance (timesteps)

typedef unsigned long long ull;

__device__ __forceinline__ ull pk2(float lo, float hi) {
    ull r;
    asm("mov.b64 %0, {%1, %2};" : "=l"(r) : "r"(__float_as_uint(lo)), "r"(__float_as_uint(hi)));
    return r;
}
__device__ __forceinline__ void upk2(ull v, float& lo, float& hi) {
    unsigned a, b2;
    asm("mov.b64 {%0, %1}, %2;" : "=r"(a), "=r"(b2) : "l"(v));
    lo = __uint_as_float(a);
    hi = __uint_as_float(b2);
}
__device__ __forceinline__ void ffma2(ull& acc, ull a, ull b) {
    asm("fma.rn.f32x2 %0, %1, %2, %0;" : "+l"(acc) : "l"(a), "l"(b));
}
__device__ __forceinline__ ull fadd2(ull a, ull b) {
    ull r;
    asm("add.rn.f32x2 %0, %1, %2;" : "=l"(r) : "l"(a), "l"(b));
    return r;
}
__device__ __forceinline__ ull fmul2(ull a, ull b) {
    ull r;
    asm("mul.rn.f32x2 %0, %1, %2;" : "=l"(r) : "l"(a), "l"(b));
    return r;
}
__device__ __forceinline__ float frcp(float x) {
    float r;
    asm("rcp.approx.f32 %0, %1;" : "=f"(r) : "f"(x));
    return r;
}
__device__ __forceinline__ float fex2(float x) {
    float r;
    asm("ex2.approx.f32 %0, %1;" : "=f"(r) : "f"(x));
    return r;
}

// Scales folded into R/bias so the activation core is gate-uniform:
//   r = rcp(1 + ex2(s));  a = fma(k, r, m)
//   sigmoid (g in {0,1,3}): s = -log2(e)*x   -> a = r        (k=1,  m=0)
//   tanh    (g == 2):       s = 2*log2(e)*x  -> a = 1 - 2r   (k=-2, m=1)
#define L2E 1.4426950408889634f

__global__ void __launch_bounds__(256, 2)
flashrnn_lstm_kernel(const float* __restrict__ Wx,
                     const float* __restrict__ S0,
                     const float* __restrict__ R,
                     const float* __restrict__ bias,
                     float* __restrict__ out)
{
    const int cell = blockIdx.x;          // 0..191
    const int n = cell % NHEADS;
    const int b = cell / NHEADS;
    const int tid  = threadIdx.x;         // 0..255
    const int warp = tid >> 5;            // 0..7
    const int lane = tid & 31;
    const int g    = lane >> 3;           // gate 0..3 (i,f,z,o) — varies within warp
    const int o    = (warp << 3) | (lane & 7);  // this thread's output element

    __shared__ __align__(16) float sh_h[2][HD];   // ping-pong hidden state

    // Per-gate activation constants (branch-free core)
    const float sg = (g == 2) ? (2.0f * L2E) : (-L2E);  // pre-activation scale
    const float kg = (g == 2) ? -2.0f : 1.0f;
    const float mg = (g == 2) ?  1.0f : 0.0f;

    // ---- Load R row R[n][g][o][0..63], pre-scaled by sg, packed f32x2 ----
    // Rp[m] multiplies h elements (2m, 2m+1).
    ull Rp[32];
    {
        const float4* rrow = reinterpret_cast<const float4*>(
            R + (((size_t)n * NG + g) * HD + o) * HD);
        const ull sg2 = pk2(sg, sg);
#pragma unroll
        for (int k = 0; k < 16; ++k) {
            float4 v = rrow[k];
            Rp[2 * k]     = fmul2(pk2(v.x, v.y), sg2);
            Rp[2 * k + 1] = fmul2(pk2(v.z, v.w), sg2);
        }
    }
    const float bvs = bias[((size_t)n * NG + g) * HD + o] * sg;  // pre-scaled bias

    // ---- Initial states (each lane owns ONE output o; c replicated x4 over g) ----
    const size_t bn = (size_t)b * NHEADS + n;
    const float h0 = S0[bn * HD + o];
    float c = S0[(size_t)NCELLS * HD + bn * HD + o];

    float* out_h = out;                                 // [1025][192][64]
    float* out_c = out + (size_t)(T_STEPS + 1) * OROW;  // second state plane

    if (g == 0) {
        sh_h[0][o] = h0;
        out_h[bn * HD + o] = h0;    // t=0 h
    } else if (g == 1) {
        out_c[bn * HD + o] = c;     // t=0 c
    }

    // ---- Wx stream pointer ----
    const float* wx = Wx + bn * CELLSTR + (size_t)o * NG + g;

    __syncthreads();

    float xc[PF];
#pragma unroll
    for (int j = 0; j < PF; ++j)
        xc[j] = __ldcs(wx + (size_t)j * TSTRIDE);

    int buf = 0;
    float* oh = out_h + OROW + bn * HD + o;   // t=1 row
    float* oc = out_c + OROW + bn * HD + o;

    for (int t0 = 0; t0 < T_STEPS; t0 += PF) {
        float xn[PF];
        const bool more = (t0 + PF) < T_STEPS;
#pragma unroll
        for (int j = 0; j < PF; ++j)
            xn[j] = more ? __ldcs(wx + (size_t)(t0 + PF + j) * TSTRIDE) : 0.0f;

#pragma unroll
        for (int j = 0; j < PF; ++j) {
            // ---- pre-activation: sg*(x + b) + (sg*R[row]) . h  (full 64-elem dot) ----
            const float xb = fmaf(xc[j], sg, bvs);      // off critical path
            ull acc[8];
            acc[0] = pk2(xb, 0.0f);
#pragma unroll
            for (int i = 1; i < 8; ++i) acc[i] = 0ULL;

            // hb[k] = h pairs (2k, 2k+1); k = 0..15 covers ALL 64 elements.
            const ulonglong2* hb = reinterpret_cast<const ulonglong2*>(sh_h[buf]);
#pragma unroll
            for (int k = 0; k < 16; ++k) {              // 16x LDS.128 broadcast
                ulonglong2 t2 = hb[k];
                ffma2(acc[(2 * k) & 7],     Rp[2 * k],     t2.x);   // pair 2k
                ffma2(acc[(2 * k + 1) & 7], Rp[2 * k + 1], t2.y);   // pair 2k+1
            }
            // fadd2 reduction tree 8 -> 1
            ull s01 = fadd2(acc[0], acc[1]);
            ull s23 = fadd2(acc[2], acc[3]);
            ull s45 = fadd2(acc[4], acc[5]);
            ull s67 = fadd2(acc[6], acc[7]);
            ull sAll = fadd2(fadd2(s01, s23), fadd2(s45, s67));
            float lo, hi;
            upk2(sAll, lo, hi);
            const float s = lo + hi;

            // ---- branch-free activation: 2 MUFU ----
            const float e = fex2(s);
            const float rv = frcp(1.0f + e);
            const float a = fmaf(kg, rv, mg);

            // ---- in-warp gate gather: 3 shuffles + select network ----
            const float bx = __shfl_xor_sync(0xffffffffu, a, 8);    // gate g^1
            const float p2 = __shfl_xor_sync(0xffffffffu, a, 16);   // gate g^2
            const float p3 = __shfl_xor_sync(0xffffffffu, bx, 16);  // gate g^3
            const bool gb0 = (g & 1);
            const bool gb1 = (g & 2);
            const float q0 = gb0 ? bx : a;    // even gate of own pair
            const float q1 = gb0 ? a : bx;    // odd gate of own pair
            const float r0 = gb0 ? p3 : p2;   // even gate of other pair
            const float r1 = gb0 ? p2 : p3;   // odd gate of other pair
            const float gi = gb1 ? r0 : q0;
            const float gf = gb1 ? r1 : q1;
            const float gz = gb1 ? q0 : r0;
            const float go = gb1 ? q1 : r1;

            // ---- cell update (4x redundant across g-lanes; identical ops) ----
            c = fmaf(gf, c, gi * gz);
            const float e2 = fex2(c * (2.0f * L2E));
            const float r2 = frcp(1.0f + e2);
            const float go2 = go + go;                  // off-chain
            const float h = fmaf(-go2, r2, go);         // go * tanh(c)

            if (g == 0) {
                sh_h[buf ^ 1][o] = h;
                *oh = h;
            } else if (g == 1) {
                *oc = c;
            }
            __syncthreads();   // the ONLY barrier per step

            buf ^= 1;
            oh += OROW;
            oc += OROW;
        }
#pragma unroll
        for (int j = 0; j < PF; ++j) xc[j] = xn[j];
    }
}

extern "C" void kernel_launch(void* const* d_in, const int* in_sizes, int n_in,
                              void* d_out, int out_size)
{
    const float* Wx   = (const float*)d_in[0];  // [1024,16,12,64,4]
    const float* S0   = (const float*)d_in[1];  // [2,16,12,64]
    const float* R    = (const float*)d_in[2];  // [12,4,64,64]
    const float* bias = (const float*)d_in[3];  // [12,4,64]
    float* out = (float*)d_out;                 // [2,1025,16,12,64]

    flashrnn_lstm_kernel<<<NCELLS, 256>>>(Wx, S0, R, bias, out);
}

// round 10
// speedup vs baseline: 1.3179x; 1.1355x over previous
#include <cuda_runtime.h>
#include <cstdint>

// Problem constants
#define T_STEPS 1024
#define BATCH   16
#define NHEADS  12
#define HD      64
#define NG      4
#define NCELLS  (BATCH * NHEADS)          // 192
#define CELLSTR (HD * NG)                 // 256 floats per (t,b,n)
#define TSTRIDE (NCELLS * CELLSTR)        // 49152 floats per timestep of Wx
#define OROW    ((size_t)NCELLS * HD)     // 12288 floats per timestep of out
#define PF      4                         // Wx prefetch distance (timesteps)

typedef unsigned long long ull;

__device__ __forceinline__ ull pk2(float lo, float hi) {
    ull r;
    asm("mov.b64 %0, {%1, %2};" : "=l"(r) : "r"(__float_as_uint(lo)), "r"(__float_as_uint(hi)));
    return r;
}
__device__ __forceinline__ void upk2(ull v, float& lo, float& hi) {
    unsigned a, b2;
    asm("mov.b64 {%0, %1}, %2;" : "=r"(a), "=r"(b2) : "l"(v));
    lo = __uint_as_float(a);
    hi = __uint_as_float(b2);
}
__device__ __forceinline__ void ffma2(ull& acc, ull a, ull b) {
    asm("fma.rn.f32x2 %0, %1, %2, %0;" : "+l"(acc) : "l"(a), "l"(b));
}
__device__ __forceinline__ ull fadd2(ull a, ull b) {
    ull r;
    asm("add.rn.f32x2 %0, %1, %2;" : "=l"(r) : "l"(a), "l"(b));
    return r;
}
__device__ __forceinline__ ull fmul2(ull a, ull b) {
    ull r;
    asm("mul.rn.f32x2 %0, %1, %2;" : "=l"(r) : "l"(a), "l"(b));
    return r;
}
__device__ __forceinline__ float frcp(float x) {
    float r;
    asm("rcp.approx.f32 %0, %1;" : "=f"(r) : "f"(x));
    return r;
}
__device__ __forceinline__ float fex2(float x) {
    float r;
    asm("ex2.approx.f32 %0, %1;" : "=f"(r) : "f"(x));
    return r;
}

// Scales folded into R/bias so the activation core is gate-uniform:
//   r = rcp(1 + ex2(s));  a = fma(k, r, m)
//   sigmoid (g in {0,1,3}): s = -log2(e)*x   -> a = r        (k=1,  m=0)
//   tanh    (g == 2):       s = 2*log2(e)*x  -> a = 1 - 2r   (k=-2, m=1)
#define L2E 1.4426950408889634f

__global__ void __launch_bounds__(128, 2)
flashrnn_lstm_kernel(const float* __restrict__ Wx,
                     const float* __restrict__ S0,
                     const float* __restrict__ R,
                     const float* __restrict__ bias,
                     float* __restrict__ out)
{
    const int cell = blockIdx.x;          // 0..191
    const int n = cell % NHEADS;
    const int b = cell / NHEADS;
    const int tid  = threadIdx.x;         // 0..127
    const int warp = tid >> 5;            // 0..3
    const int lane = tid & 31;
    const int g    = lane >> 3;           // gate 0..3 (i,f,z,o)
    const int oA   = (warp << 3) | (lane & 7);  // first owned output (0..31)
    const int oB   = oA + 32;                   // second owned output (32..63)

    __shared__ __align__(16) float sh_h[2][HD];   // ping-pong hidden state

    // Per-gate activation constants (branch-free core)
    const float sg = (g == 2) ? (2.0f * L2E) : (-L2E);
    const float kg = (g == 2) ? -2.0f : 1.0f;
    const float mg = (g == 2) ?  1.0f : 0.0f;

    // ---- R rows for both slots, pre-scaled by sg, packed f32x2 ----
    // RpA[m]/RpB[m] multiply h elements (2m, 2m+1).
    ull RpA[32], RpB[32];
    {
        const ull sg2 = pk2(sg, sg);
        const float4* rA = reinterpret_cast<const float4*>(
            R + (((size_t)n * NG + g) * HD + oA) * HD);
        const float4* rB = reinterpret_cast<const float4*>(
            R + (((size_t)n * NG + g) * HD + oB) * HD);
#pragma unroll
        for (int k = 0; k < 16; ++k) {
            float4 vA = rA[k];
            float4 vB = rB[k];
            RpA[2 * k]     = fmul2(pk2(vA.x, vA.y), sg2);
            RpA[2 * k + 1] = fmul2(pk2(vA.z, vA.w), sg2);
            RpB[2 * k]     = fmul2(pk2(vB.x, vB.y), sg2);
            RpB[2 * k + 1] = fmul2(pk2(vB.z, vB.w), sg2);
        }
    }
    const float bvsA = bias[((size_t)n * NG + g) * HD + oA] * sg;
    const float bvsB = bias[((size_t)n * NG + g) * HD + oB] * sg;

    // ---- Initial states (c replicated x4 over g-lanes per output) ----
    const size_t bn = (size_t)b * NHEADS + n;
    const float h0A = S0[bn * HD + oA];
    const float h0B = S0[bn * HD + oB];
    float cA = S0[(size_t)NCELLS * HD + bn * HD + oA];
    float cB = S0[(size_t)NCELLS * HD + bn * HD + oB];

    float* out_h = out;                                 // [1025][192][64]
    float* out_c = out + (size_t)(T_STEPS + 1) * OROW;  // second state plane

    if (g == 0) {
        sh_h[0][oA] = h0A;
        sh_h[0][oB] = h0B;
        out_h[bn * HD + oA] = h0A;   // t=0 h
        out_h[bn * HD + oB] = h0B;
    } else if (g == 1) {
        out_c[bn * HD + oA] = cA;    // t=0 c
        out_c[bn * HD + oB] = cB;
    }

    // ---- Wx stream pointers (slot B is +32*NG floats from slot A) ----
    const float* wxA = Wx + bn * CELLSTR + (size_t)oA * NG + g;

    __syncthreads();

    float xcA[PF], xcB[PF];
#pragma unroll
    for (int j = 0; j < PF; ++j) {
        xcA[j] = __ldcs(wxA + (size_t)j * TSTRIDE);
        xcB[j] = __ldcs(wxA + (size_t)j * TSTRIDE + 32 * NG);
    }

    int buf = 0;
    float* oh = out_h + OROW + bn * HD + oA;   // t=1 row, slot A; slot B = +32
    float* oc = out_c + OROW + bn * HD + oA;

    for (int t0 = 0; t0 < T_STEPS; t0 += PF) {
        float xnA[PF], xnB[PF];
        const bool more = (t0 + PF) < T_STEPS;
#pragma unroll
        for (int j = 0; j < PF; ++j) {
            const float* p = wxA + (size_t)(t0 + PF + j) * TSTRIDE;
            xnA[j] = more ? __ldcs(p) : 0.0f;
            xnB[j] = more ? __ldcs(p + 32 * NG) : 0.0f;
        }

#pragma unroll
        for (int j = 0; j < PF; ++j) {
            // ---- two pre-activation dots, shared h loads ----
            const float xbA = fmaf(xcA[j], sg, bvsA);
            const float xbB = fmaf(xcB[j], sg, bvsB);
            ull accA[4], accB[4];
            accA[0] = pk2(xbA, 0.0f);
            accB[0] = pk2(xbB, 0.0f);
#pragma unroll
            for (int i = 1; i < 4; ++i) { accA[i] = 0ULL; accB[i] = 0ULL; }

            const ulonglong2* hb = reinterpret_cast<const ulonglong2*>(sh_h[buf]);
#pragma unroll
            for (int k = 0; k < 16; ++k) {             // 16x LDS.128 broadcast
                ulonglong2 t2 = hb[k];
                ffma2(accA[(2 * k) & 3],     RpA[2 * k],     t2.x);
                ffma2(accA[(2 * k + 1) & 3], RpA[2 * k + 1], t2.y);
                ffma2(accB[(2 * k) & 3],     RpB[2 * k],     t2.x);
                ffma2(accB[(2 * k + 1) & 3], RpB[2 * k + 1], t2.y);
            }
            ull sa = fadd2(fadd2(accA[0], accA[1]), fadd2(accA[2], accA[3]));
            ull sb = fadd2(fadd2(accB[0], accB[1]), fadd2(accB[2], accB[3]));
            float lo, hi;
            upk2(sa, lo, hi); const float sA = lo + hi;
            upk2(sb, lo, hi); const float sB = lo + hi;

            // ---- branch-free activations (two independent chains) ----
            const float aA = fmaf(kg, frcp(1.0f + fex2(sA)), mg);
            const float aB = fmaf(kg, frcp(1.0f + fex2(sB)), mg);

            // ---- in-warp gate gather: 3 PARALLEL shuffles per slot ----
            // lane^8 -> gate g^1, lane^16 -> gate g^2, lane^24 -> gate g^3 (same o)
            const float a1A = __shfl_xor_sync(0xffffffffu, aA, 8);
            const float a2A = __shfl_xor_sync(0xffffffffu, aA, 16);
            const float a3A = __shfl_xor_sync(0xffffffffu, aA, 24);
            const float a1B = __shfl_xor_sync(0xffffffffu, aB, 8);
            const float a2B = __shfl_xor_sync(0xffffffffu, aB, 16);
            const float a3B = __shfl_xor_sync(0xffffffffu, aB, 24);
            // val[d] = gate (g^d); gate q = val[q^g]
            const bool gb0 = (g & 1);
            const bool gb1 = (g & 2);
            // slot A selects
            const float t0A = gb0 ? a1A : aA;    // idx bit0=gb0 of {val0,val1}
            const float t1A = gb0 ? a3A : a2A;   // of {val2,val3}
            const float u0A = gb0 ? aA  : a1A;   // idx bit0=!gb0
            const float u1A = gb0 ? a2A : a3A;
            const float giA = gb1 ? t1A : t0A;   // val[g]
            const float gfA = gb1 ? u1A : u0A;   // val[1^g]
            const float gzA = gb1 ? t0A : t1A;   // val[2^g]
            const float goA = gb1 ? u0A : u1A;   // val[3^g]
            // slot B selects
            const float t0B = gb0 ? a1B : aB;
            const float t1B = gb0 ? a3B : a2B;
            const float u0B = gb0 ? aB  : a1B;
            const float u1B = gb0 ? a2B : a3B;
            const float giB = gb1 ? t1B : t0B;
            const float gfB = gb1 ? u1B : u0B;
            const float gzB = gb1 ? t0B : t1B;
            const float goB = gb1 ? u0B : u1B;

            // ---- cell updates (4x redundant across g-lanes; identical ops) ----
            cA = fmaf(gfA, cA, giA * gzA);
            cB = fmaf(gfB, cB, giB * gzB);
            const float rA2 = frcp(1.0f + fex2(cA * (2.0f * L2E)));
            const float rB2 = frcp(1.0f + fex2(cB * (2.0f * L2E)));
            const float hA = fmaf(-(goA + goA), rA2, goA);   // goA * tanh(cA)
            const float hB = fmaf(-(goB + goB), rB2, goB);

            if (g == 0) {
                sh_h[buf ^ 1][oA] = hA;
                sh_h[buf ^ 1][oB] = hB;
                oh[0]  = hA;
                oh[32] = hB;
            } else if (g == 1) {
                oc[0]  = cA;
                oc[32] = cB;
            }
            __syncthreads();   // the ONLY barrier per step (4 warps)

            buf ^= 1;
            oh += OROW;
            oc += OROW;
        }
#pragma unroll
        for (int j = 0; j < PF; ++j) { xcA[j] = xnA[j]; xcB[j] = xnB[j]; }
    }
}

extern "C" void kernel_launch(void* const* d_in, const int* in_sizes, int n_in,
                              void* d_out, int out_size)
{
    const float* Wx   = (const float*)d_in[0];  // [1024,16,12,64,4]
    const float* S0   = (const float*)d_in[1];  // [2,16,12,64]
    const float* R    = (const float*)d_in[2];  // [12,4,64,64]
    const float* bias = (const float*)d_in[3];  // [12,4,64]
    float* out = (float*)d_out;                 // [2,1025,16,12,64]

    flashrnn_lstm_kernel<<<NCELLS, 128>>>(Wx, S0, R, bias, out);
}